// round 1
// baseline (speedup 1.0000x reference)
#include <cuda_runtime.h>
#include <cuda_bf16.h>
#include <cstdint>

#define NMAX 100000
#define EMAX 1600000
#define DD   64
#define NEG_SLOPE 0.01f

// -------- device scratch (no allocation allowed) --------
__device__ float g_dinv[NMAX];
__device__ int   g_deg[NMAX];
__device__ float g_h[NMAX * DD];      // h = act(in) @ W for current layer
__device__ float g_buf0[NMAX * DD];   // ping-pong layer outputs (pre-activation)
__device__ float g_buf1[NMAX * DD];

// -------- degree / dinv --------
__global__ void k_zero_deg(int n) {
    int i = blockIdx.x * blockDim.x + threadIdx.x;
    if (i < n) g_deg[i] = 0;
}

__global__ void k_count_deg(const int* __restrict__ dst, int e) {
    int i = blockIdx.x * blockDim.x + threadIdx.x;
    if (i < e) atomicAdd(&g_deg[dst[i]], 1);
}

__global__ void k_dinv(int n) {
    int i = blockIdx.x * blockDim.x + threadIdx.x;
    if (i < n) g_dinv[i] = rsqrtf((float)g_deg[i] + 1.0f);
}

// -------- fused GEMM: h = act(in) @ W ; out = dinv^2 * h + b --------
// block: 256 threads -> 64 rows x 4 column-groups of 16
__global__ __launch_bounds__(256) void k_gemm(
    const float* __restrict__ in, const float* __restrict__ W,
    const float* __restrict__ b, float* __restrict__ h,
    float* __restrict__ out, int n, int leaky_in)
{
    __shared__ float xs[64][DD + 1];   // +1 pad: kill bank conflicts
    __shared__ float ws[DD][DD];

    int t = threadIdx.x;
    int row0 = blockIdx.x * 64;

    // load W tile (4096 floats, 16 per thread, coalesced)
    #pragma unroll
    for (int k = 0; k < 16; k++) {
        int idx = t + k * 256;
        ws[idx >> 6][idx & 63] = W[idx];
    }
    // load x tile with optional LeakyReLU on input
    #pragma unroll
    for (int k = 0; k < 16; k++) {
        int idx = t + k * 256;
        int r = idx >> 6, c = idx & 63;
        int gr = row0 + r;
        float v = 0.0f;
        if (gr < n) {
            v = in[gr * DD + c];
            if (leaky_in) v = (v >= 0.0f) ? v : NEG_SLOPE * v;
        }
        xs[r][c] = v;
    }
    __syncthreads();

    int row = t >> 2;          // 0..63
    int cg  = (t & 3) * 16;    // 0,16,32,48

    float acc[16];
    #pragma unroll
    for (int j = 0; j < 16; j++) acc[j] = 0.0f;

    #pragma unroll 8
    for (int k = 0; k < DD; k++) {
        float xv = xs[row][k];
        #pragma unroll
        for (int j = 0; j < 16; j++)
            acc[j] = fmaf(xv, ws[k][cg + j], acc[j]);
    }

    int gr = row0 + row;
    if (gr < n) {
        float di = g_dinv[gr];
        float d2 = di * di;
        float* hp = &h[gr * DD + cg];
        float* op = &out[gr * DD + cg];
        #pragma unroll
        for (int j = 0; j < 16; j += 4) {
            float4 hv = make_float4(acc[j], acc[j+1], acc[j+2], acc[j+3]);
            *(float4*)(hp + j) = hv;
            float4 ov = make_float4(
                d2 * acc[j]   + b[cg + j],
                d2 * acc[j+1] + b[cg + j + 1],
                d2 * acc[j+2] + b[cg + j + 2],
                d2 * acc[j+3] + b[cg + j + 3]);
            *(float4*)(op + j) = ov;
        }
    }
}

// -------- edge scatter: out[dst] += dinv[src]*dinv[dst] * h[src] --------
// 16 threads per edge, float4 per thread, vectorized red.global
__global__ __launch_bounds__(256) void k_scatter(
    const int* __restrict__ src, const int* __restrict__ dst,
    const float* __restrict__ h, float* __restrict__ out, int e)
{
    int idx = blockIdx.x * blockDim.x + threadIdx.x;
    int eid  = idx >> 4;
    int lane = (idx & 15) << 2;   // float offset 0..60 step 4
    if (eid >= e) return;
    int s = __ldg(&src[eid]);
    int d = __ldg(&dst[eid]);
    float c = g_dinv[s] * g_dinv[d];
    float4 v = __ldg((const float4*)&h[s * DD + lane]);
    v.x *= c; v.y *= c; v.z *= c; v.w *= c;
    float* p = &out[d * DD + lane];
    asm volatile("red.global.add.v4.f32 [%0], {%1,%2,%3,%4};"
                 :: "l"(p), "f"(v.x), "f"(v.y), "f"(v.z), "f"(v.w)
                 : "memory");
}

// -------- final activation into d_out --------
__global__ void k_leaky_out(const float* __restrict__ in, float* __restrict__ out, int total) {
    int i = blockIdx.x * blockDim.x + threadIdx.x;
    if (i < total) {
        float v = in[i];
        out[i] = (v >= 0.0f) ? v : NEG_SLOPE * v;
    }
}

extern "C" void kernel_launch(void* const* d_in, const int* in_sizes, int n_in,
                              void* d_out, int out_size)
{
    const float* x  = (const float*)d_in[0];
    const int*   ei = (const int*)d_in[1];
    const float* W[4] = { (const float*)d_in[2], (const float*)d_in[4],
                          (const float*)d_in[6], (const float*)d_in[8] };
    const float* B[4] = { (const float*)d_in[3], (const float*)d_in[5],
                          (const float*)d_in[7], (const float*)d_in[9] };
    float* outp = (float*)d_out;

    int n = in_sizes[0] / DD;
    int e = in_sizes[1] / 2;
    const int* src = ei;
    const int* dst = ei + e;

    float* hbuf;  cudaGetSymbolAddress((void**)&hbuf,  g_h);
    float* buf0;  cudaGetSymbolAddress((void**)&buf0,  g_buf0);
    float* buf1;  cudaGetSymbolAddress((void**)&buf1,  g_buf1);

    // degree + dinv (recomputed per replay: deterministic)
    k_zero_deg<<<(n + 255) / 256, 256>>>(n);
    k_count_deg<<<(e + 255) / 256, 256>>>(dst, e);
    k_dinv<<<(n + 255) / 256, 256>>>(n);

    int gemm_blocks = (n + 63) / 64;
    long scat_threads = (long)e * 16;
    int scat_blocks = (int)((scat_threads + 255) / 256);

    const float* cur_in = x;
    float* bufs[2] = { buf0, buf1 };
    float* cur_out = nullptr;
    for (int l = 0; l < 4; l++) {
        cur_out = bufs[l & 1];
        k_gemm<<<gemm_blocks, 256>>>(cur_in, W[l], B[l], hbuf, cur_out, n, l > 0 ? 1 : 0);
        k_scatter<<<scat_blocks, 256>>>(src, dst, hbuf, cur_out, e);
        cur_in = cur_out;
    }

    int total = n * DD;
    k_leaky_out<<<(total + 255) / 256, 256>>>(cur_out, outp, total);
}

// round 2
// speedup vs baseline: 2.4499x; 2.4499x over previous
#include <cuda_runtime.h>
#include <cuda_bf16.h>
#include <cstdint>

#define NMAX 100000
#define EMAX 1600000
#define DD   64
#define NEG_SLOPE 0.01f

// -------- device scratch (no allocation allowed) --------
__device__ float g_dinv[NMAX];
__device__ int   g_deg[NMAX];
__device__ int   g_cursor[NMAX];
__device__ int   g_rowstart[NMAX + 1];
__device__ int   g_csr_src[EMAX];
__device__ float g_csr_coef[EMAX];
__device__ float g_h[NMAX * DD];      // h = act(in) @ W for current layer
__device__ float g_buf[NMAX * DD];    // layer output (pre-activation)

// -------- degree / dinv --------
__global__ void k_zero(int n) {
    int i = blockIdx.x * blockDim.x + threadIdx.x;
    if (i < n) { g_deg[i] = 0; g_cursor[i] = 0; }
}

__global__ void k_count_deg(const int* __restrict__ dst, int e) {
    int i = blockIdx.x * blockDim.x + threadIdx.x;
    if (i < e) atomicAdd(&g_deg[dst[i]], 1);
}

__global__ void k_dinv(int n) {
    int i = blockIdx.x * blockDim.x + threadIdx.x;
    if (i < n) g_dinv[i] = rsqrtf((float)g_deg[i] + 1.0f);
}

// -------- exclusive prefix sum of deg -> rowstart (single block) --------
__global__ __launch_bounds__(1024) void k_scan(int n) {
    __shared__ int wsum[32];
    __shared__ int s_carry;
    int t = threadIdx.x, lane = t & 31, wid = t >> 5;
    if (t == 0) s_carry = 0;
    __syncthreads();
    for (int base = 0; base < n; base += 1024) {
        int idx = base + t;
        int v = (idx < n) ? g_deg[idx] : 0;
        int x = v;
        #pragma unroll
        for (int off = 1; off < 32; off <<= 1) {
            int u = __shfl_up_sync(0xffffffffu, x, off);
            if (lane >= off) x += u;
        }
        if (lane == 31) wsum[wid] = x;
        __syncthreads();
        if (wid == 0) {
            int y = wsum[lane];
            #pragma unroll
            for (int off = 1; off < 32; off <<= 1) {
                int u = __shfl_up_sync(0xffffffffu, y, off);
                if (lane >= off) y += u;
            }
            wsum[lane] = y;
        }
        __syncthreads();
        int prefix = s_carry + (wid ? wsum[wid - 1] : 0);
        if (idx < n) g_rowstart[idx] = prefix + x - v;  // exclusive
        __syncthreads();
        if (t == 1023) s_carry = s_carry + wsum[31];
        __syncthreads();
    }
    if (t == 0) g_rowstart[n] = s_carry;
}

// -------- CSR fill (order within a row nondeterministic; sum within tol) ----
__global__ void k_fill(const int* __restrict__ src, const int* __restrict__ dst, int e) {
    int i = blockIdx.x * blockDim.x + threadIdx.x;
    if (i >= e) return;
    int s = src[i], d = dst[i];
    int pos = atomicAdd(&g_cursor[d], 1);
    int idx = g_rowstart[d] + pos;
    g_csr_src[idx]  = s;
    g_csr_coef[idx] = g_dinv[s] * g_dinv[d];
}

// -------- GEMM: h = act(in) @ W  (64 rows x 64 cols per block, 4x4 tiles) ---
__global__ __launch_bounds__(256) void k_gemm(
    const float* __restrict__ in, const float* __restrict__ W,
    float* __restrict__ h, int n, int leaky_in)
{
    __shared__ float xs[64][68];   // row-major, odd-ish pad
    __shared__ float ws[64][64];

    int t = threadIdx.x;
    int row0 = blockIdx.x * 64;

    #pragma unroll
    for (int k = 0; k < 16; k++) {
        int idx = t + k * 256;
        ws[idx >> 6][idx & 63] = W[idx];
    }
    #pragma unroll
    for (int k = 0; k < 16; k++) {
        int idx = t + k * 256;
        int r = idx >> 6, c = idx & 63;
        int gr = row0 + r;
        float v = 0.0f;
        if (gr < n) {
            v = in[gr * DD + c];
            if (leaky_in) v = (v >= 0.0f) ? v : NEG_SLOPE * v;
        }
        xs[r][c] = v;
    }
    __syncthreads();

    int cg = (t & 15) * 4;   // 4 output cols
    int rg = (t >> 4) * 4;   // 4 output rows

    float acc[4][4];
    #pragma unroll
    for (int i = 0; i < 4; i++)
        #pragma unroll
        for (int j = 0; j < 4; j++) acc[i][j] = 0.0f;

    #pragma unroll
    for (int k = 0; k < DD; k++) {
        float4 wv = *(const float4*)&ws[k][cg];
        float x0 = xs[rg + 0][k];
        float x1 = xs[rg + 1][k];
        float x2 = xs[rg + 2][k];
        float x3 = xs[rg + 3][k];
        acc[0][0] = fmaf(x0, wv.x, acc[0][0]); acc[0][1] = fmaf(x0, wv.y, acc[0][1]);
        acc[0][2] = fmaf(x0, wv.z, acc[0][2]); acc[0][3] = fmaf(x0, wv.w, acc[0][3]);
        acc[1][0] = fmaf(x1, wv.x, acc[1][0]); acc[1][1] = fmaf(x1, wv.y, acc[1][1]);
        acc[1][2] = fmaf(x1, wv.z, acc[1][2]); acc[1][3] = fmaf(x1, wv.w, acc[1][3]);
        acc[2][0] = fmaf(x2, wv.x, acc[2][0]); acc[2][1] = fmaf(x2, wv.y, acc[2][1]);
        acc[2][2] = fmaf(x2, wv.z, acc[2][2]); acc[2][3] = fmaf(x2, wv.w, acc[2][3]);
        acc[3][0] = fmaf(x3, wv.x, acc[3][0]); acc[3][1] = fmaf(x3, wv.y, acc[3][1]);
        acc[3][2] = fmaf(x3, wv.z, acc[3][2]); acc[3][3] = fmaf(x3, wv.w, acc[3][3]);
    }

    #pragma unroll
    for (int i = 0; i < 4; i++) {
        int gr = row0 + rg + i;
        if (gr < n) {
            float4 v = make_float4(acc[i][0], acc[i][1], acc[i][2], acc[i][3]);
            *(float4*)&h[gr * DD + cg] = v;
        }
    }
}

// -------- pull aggregation: out[n] = sum coef*h[src] + dinv^2*h[n] + b -------
// 16 threads per node (one float4 each), 16 nodes per block
__global__ __launch_bounds__(256) void k_pull(
    const float* __restrict__ h, const float* __restrict__ b,
    float* __restrict__ out, int n, int apply_leaky)
{
    int t = threadIdx.x;
    int node = blockIdx.x * 16 + (t >> 4);
    int lane = (t & 15) << 2;
    if (node >= n) return;

    int start = g_rowstart[node];
    int end   = g_rowstart[node + 1];

    float4 acc = make_float4(0.f, 0.f, 0.f, 0.f);
    int i = start;
    for (; i + 1 < end; i += 2) {
        int   s0 = __ldg(&g_csr_src[i]);
        float c0 = __ldg(&g_csr_coef[i]);
        int   s1 = __ldg(&g_csr_src[i + 1]);
        float c1 = __ldg(&g_csr_coef[i + 1]);
        float4 h0 = __ldg((const float4*)&h[s0 * DD + lane]);
        float4 h1 = __ldg((const float4*)&h[s1 * DD + lane]);
        acc.x = fmaf(c0, h0.x, acc.x); acc.y = fmaf(c0, h0.y, acc.y);
        acc.z = fmaf(c0, h0.z, acc.z); acc.w = fmaf(c0, h0.w, acc.w);
        acc.x = fmaf(c1, h1.x, acc.x); acc.y = fmaf(c1, h1.y, acc.y);
        acc.z = fmaf(c1, h1.z, acc.z); acc.w = fmaf(c1, h1.w, acc.w);
    }
    if (i < end) {
        int   s0 = __ldg(&g_csr_src[i]);
        float c0 = __ldg(&g_csr_coef[i]);
        float4 h0 = __ldg((const float4*)&h[s0 * DD + lane]);
        acc.x = fmaf(c0, h0.x, acc.x); acc.y = fmaf(c0, h0.y, acc.y);
        acc.z = fmaf(c0, h0.z, acc.z); acc.w = fmaf(c0, h0.w, acc.w);
    }

    float di = g_dinv[node];
    float d2 = di * di;
    float4 hv = __ldg((const float4*)&h[node * DD + lane]);
    float4 bv = __ldg((const float4*)&b[lane]);
    float4 r;
    r.x = acc.x + d2 * hv.x + bv.x;
    r.y = acc.y + d2 * hv.y + bv.y;
    r.z = acc.z + d2 * hv.z + bv.z;
    r.w = acc.w + d2 * hv.w + bv.w;
    if (apply_leaky) {
        r.x = (r.x >= 0.f) ? r.x : NEG_SLOPE * r.x;
        r.y = (r.y >= 0.f) ? r.y : NEG_SLOPE * r.y;
        r.z = (r.z >= 0.f) ? r.z : NEG_SLOPE * r.z;
        r.w = (r.w >= 0.f) ? r.w : NEG_SLOPE * r.w;
    }
    *(float4*)&out[node * DD + lane] = r;
}

extern "C" void kernel_launch(void* const* d_in, const int* in_sizes, int n_in,
                              void* d_out, int out_size)
{
    const float* x  = (const float*)d_in[0];
    const int*   ei = (const int*)d_in[1];
    const float* W[4] = { (const float*)d_in[2], (const float*)d_in[4],
                          (const float*)d_in[6], (const float*)d_in[8] };
    const float* B[4] = { (const float*)d_in[3], (const float*)d_in[5],
                          (const float*)d_in[7], (const float*)d_in[9] };
    float* outp = (float*)d_out;

    int n = in_sizes[0] / DD;
    int e = in_sizes[1] / 2;
    const int* src = ei;
    const int* dst = ei + e;

    float* hbuf; cudaGetSymbolAddress((void**)&hbuf, g_h);
    float* buf;  cudaGetSymbolAddress((void**)&buf,  g_buf);

    // ---- CSR build (per replay; deterministic work) ----
    k_zero<<<(n + 255) / 256, 256>>>(n);
    k_count_deg<<<(e + 255) / 256, 256>>>(dst, e);
    k_dinv<<<(n + 255) / 256, 256>>>(n);
    k_scan<<<1, 1024>>>(n);
    k_fill<<<(e + 255) / 256, 256>>>(src, dst, e);

    int gemm_blocks = (n + 63) / 64;
    int pull_blocks = (n + 15) / 16;

    const float* cur_in = x;
    for (int l = 0; l < 4; l++) {
        float* layer_out = (l == 3) ? outp : buf;
        k_gemm<<<gemm_blocks, 256>>>(cur_in, W[l], hbuf, n, l > 0 ? 1 : 0);
        k_pull<<<pull_blocks, 256>>>(hbuf, B[l], layer_out, n, (l == 3) ? 1 : 0);
        cur_in = buf;
    }
}

// round 7
// speedup vs baseline: 2.8601x; 1.1674x over previous
#include <cuda_runtime.h>
#include <cuda_bf16.h>
#include <cstdint>

#define NMAX 100000
#define EMAX 1600000
#define DD   64
#define NEG_SLOPE 0.01f
#define SCAN_BLK 1024
#define MAX_SBLKS 256

// -------- device scratch (no allocation allowed) --------
__device__ float g_dinv[NMAX];
__device__ int   g_deg[NMAX];
__device__ int   g_cursor[NMAX];
__device__ int   g_rowstart[NMAX + 1];
__device__ int   g_bsums[MAX_SBLKS];
__device__ int   g_csr_src[EMAX];
__device__ float g_csr_coef[EMAX];
__device__ float g_h[NMAX * DD];      // h = act(in) @ W for current layer
__device__ float g_buf[NMAX * DD];    // layer output (pre-activation)

// -------- degree / dinv --------
__global__ void k_zero(int n) {
    int i = blockIdx.x * blockDim.x + threadIdx.x;
    if (i < n) { g_deg[i] = 0; g_cursor[i] = 0; }
}

__global__ void k_count_deg(const int* __restrict__ dst, int e) {
    int i = blockIdx.x * blockDim.x + threadIdx.x;
    if (i < e) atomicAdd(&g_deg[dst[i]], 1);
}

__global__ void k_dinv(int n) {
    int i = blockIdx.x * blockDim.x + threadIdx.x;
    if (i < n) g_dinv[i] = rsqrtf((float)g_deg[i] + 1.0f);
}

// -------- multi-block exclusive scan of deg -> rowstart --------
// phase 1: per-block local exclusive scan, block totals to g_bsums
__global__ __launch_bounds__(SCAN_BLK) void k_scan1(int n) {
    __shared__ int wsum[32];
    int t = threadIdx.x, lane = t & 31, wid = t >> 5;
    int idx = blockIdx.x * SCAN_BLK + t;
    int v = (idx < n) ? g_deg[idx] : 0;
    int x = v;
    #pragma unroll
    for (int off = 1; off < 32; off <<= 1) {
        int u = __shfl_up_sync(0xffffffffu, x, off);
        if (lane >= off) x += u;
    }
    if (lane == 31) wsum[wid] = x;
    __syncthreads();
    if (wid == 0) {
        int y = wsum[lane];
        #pragma unroll
        for (int off = 1; off < 32; off <<= 1) {
            int u = __shfl_up_sync(0xffffffffu, y, off);
            if (lane >= off) y += u;
        }
        wsum[lane] = y;
    }
    __syncthreads();
    int prefix = (wid ? wsum[wid - 1] : 0);
    if (idx < n) g_rowstart[idx] = prefix + x - v;   // local exclusive
    if (t == SCAN_BLK - 1) g_bsums[blockIdx.x] = wsum[31];
}

// phase 2: single block scans block totals (exclusive, in place), writes total
__global__ __launch_bounds__(MAX_SBLKS) void k_scan2(int nblocks, int n) {
    __shared__ int sh[MAX_SBLKS];
    int t = threadIdx.x;
    int v = (t < nblocks) ? g_bsums[t] : 0;
    sh[t] = v;
    __syncthreads();
    // Hillis-Steele inclusive
    for (int off = 1; off < MAX_SBLKS; off <<= 1) {
        int u = (t >= off) ? sh[t - off] : 0;
        __syncthreads();
        sh[t] += u;
        __syncthreads();
    }
    if (t < nblocks) g_bsums[t] = sh[t] - v;   // exclusive
    if (t == MAX_SBLKS - 1) g_rowstart[n] = sh[MAX_SBLKS - 1];
}

// phase 3: add block offsets
__global__ __launch_bounds__(SCAN_BLK) void k_scan3(int n) {
    int idx = blockIdx.x * SCAN_BLK + threadIdx.x;
    if (idx < n) g_rowstart[idx] += g_bsums[blockIdx.x];
}

// -------- CSR fill (order within a row nondeterministic; sum within tol) ----
__global__ void k_fill(const int* __restrict__ src, const int* __restrict__ dst, int e) {
    int i = blockIdx.x * blockDim.x + threadIdx.x;
    if (i >= e) return;
    int s = src[i], d = dst[i];
    int pos = atomicAdd(&g_cursor[d], 1);
    int idx = g_rowstart[d] + pos;
    g_csr_src[idx]  = s;
    g_csr_coef[idx] = g_dinv[s] * g_dinv[d];
}

// -------- GEMM: h = act(in) @ W  (64 rows x 64 cols per block, 4x4 tiles) ---
__global__ __launch_bounds__(256) void k_gemm(
    const float* __restrict__ in, const float* __restrict__ W,
    float* __restrict__ h, int n, int leaky_in)
{
    __shared__ float xs[64][68];
    __shared__ float ws[64][64];

    int t = threadIdx.x;
    int row0 = blockIdx.x * 64;

    #pragma unroll
    for (int k = 0; k < 16; k++) {
        int idx = t + k * 256;
        ws[idx >> 6][idx & 63] = W[idx];
    }
    #pragma unroll
    for (int k = 0; k < 16; k++) {
        int idx = t + k * 256;
        int r = idx >> 6, c = idx & 63;
        int gr = row0 + r;
        float v = 0.0f;
        if (gr < n) {
            v = in[gr * DD + c];
            if (leaky_in) v = (v >= 0.0f) ? v : NEG_SLOPE * v;
        }
        xs[r][c] = v;
    }
    __syncthreads();

    int cg = (t & 15) * 4;
    int rg = (t >> 4) * 4;

    float acc[4][4];
    #pragma unroll
    for (int i = 0; i < 4; i++)
        #pragma unroll
        for (int j = 0; j < 4; j++) acc[i][j] = 0.0f;

    #pragma unroll
    for (int k = 0; k < DD; k++) {
        float4 wv = *(const float4*)&ws[k][cg];
        float x0 = xs[rg + 0][k];
        float x1 = xs[rg + 1][k];
        float x2 = xs[rg + 2][k];
        float x3 = xs[rg + 3][k];
        acc[0][0] = fmaf(x0, wv.x, acc[0][0]); acc[0][1] = fmaf(x0, wv.y, acc[0][1]);
        acc[0][2] = fmaf(x0, wv.z, acc[0][2]); acc[0][3] = fmaf(x0, wv.w, acc[0][3]);
        acc[1][0] = fmaf(x1, wv.x, acc[1][0]); acc[1][1] = fmaf(x1, wv.y, acc[1][1]);
        acc[1][2] = fmaf(x1, wv.z, acc[1][2]); acc[1][3] = fmaf(x1, wv.w, acc[1][3]);
        acc[2][0] = fmaf(x2, wv.x, acc[2][0]); acc[2][1] = fmaf(x2, wv.y, acc[2][1]);
        acc[2][2] = fmaf(x2, wv.z, acc[2][2]); acc[2][3] = fmaf(x2, wv.w, acc[2][3]);
        acc[3][0] = fmaf(x3, wv.x, acc[3][0]); acc[3][1] = fmaf(x3, wv.y, acc[3][1]);
        acc[3][2] = fmaf(x3, wv.z, acc[3][2]); acc[3][3] = fmaf(x3, wv.w, acc[3][3]);
    }

    #pragma unroll
    for (int i = 0; i < 4; i++) {
        int gr = row0 + rg + i;
        if (gr < n) {
            float4 v = make_float4(acc[i][0], acc[i][1], acc[i][2], acc[i][3]);
            *(float4*)&h[gr * DD + cg] = v;
        }
    }
}

// -------- pull aggregation: out[n] = sum coef*h[src] + dinv^2*h[n] + b -------
__global__ __launch_bounds__(256) void k_pull(
    const float* __restrict__ h, const float* __restrict__ b,
    float* __restrict__ out, int n, int apply_leaky)
{
    int t = threadIdx.x;
    int node = blockIdx.x * 16 + (t >> 4);
    int lane = (t & 15) << 2;
    if (node >= n) return;

    int start = g_rowstart[node];
    int end   = g_rowstart[node + 1];

    float4 acc = make_float4(0.f, 0.f, 0.f, 0.f);
    int i = start;
    for (; i + 1 < end; i += 2) {
        int   s0 = __ldg(&g_csr_src[i]);
        float c0 = __ldg(&g_csr_coef[i]);
        int   s1 = __ldg(&g_csr_src[i + 1]);
        float c1 = __ldg(&g_csr_coef[i + 1]);
        float4 h0 = __ldg((const float4*)&h[s0 * DD + lane]);
        float4 h1 = __ldg((const float4*)&h[s1 * DD + lane]);
        acc.x = fmaf(c0, h0.x, acc.x); acc.y = fmaf(c0, h0.y, acc.y);
        acc.z = fmaf(c0, h0.z, acc.z); acc.w = fmaf(c0, h0.w, acc.w);
        acc.x = fmaf(c1, h1.x, acc.x); acc.y = fmaf(c1, h1.y, acc.y);
        acc.z = fmaf(c1, h1.z, acc.z); acc.w = fmaf(c1, h1.w, acc.w);
    }
    if (i < end) {
        int   s0 = __ldg(&g_csr_src[i]);
        float c0 = __ldg(&g_csr_coef[i]);
        float4 h0 = __ldg((const float4*)&h[s0 * DD + lane]);
        acc.x = fmaf(c0, h0.x, acc.x); acc.y = fmaf(c0, h0.y, acc.y);
        acc.z = fmaf(c0, h0.z, acc.z); acc.w = fmaf(c0, h0.w, acc.w);
    }

    float di = g_dinv[node];
    float d2 = di * di;
    float4 hv = __ldg((const float4*)&h[node * DD + lane]);
    float4 bv = __ldg((const float4*)&b[lane]);
    float4 r;
    r.x = acc.x + d2 * hv.x + bv.x;
    r.y = acc.y + d2 * hv.y + bv.y;
    r.z = acc.z + d2 * hv.z + bv.z;
    r.w = acc.w + d2 * hv.w + bv.w;
    if (apply_leaky) {
        r.x = (r.x >= 0.f) ? r.x : NEG_SLOPE * r.x;
        r.y = (r.y >= 0.f) ? r.y : NEG_SLOPE * r.y;
        r.z = (r.z >= 0.f) ? r.z : NEG_SLOPE * r.z;
        r.w = (r.w >= 0.f) ? r.w : NEG_SLOPE * r.w;
    }
    *(float4*)&out[node * DD + lane] = r;
}

extern "C" void kernel_launch(void* const* d_in, const int* in_sizes, int n_in,
                              void* d_out, int out_size)
{
    const float* x  = (const float*)d_in[0];
    const int*   ei = (const int*)d_in[1];
    const float* W[4] = { (const float*)d_in[2], (const float*)d_in[4],
                          (const float*)d_in[6], (const float*)d_in[8] };
    const float* B[4] = { (const float*)d_in[3], (const float*)d_in[5],
                          (const float*)d_in[7], (const float*)d_in[9] };
    float* outp = (float*)d_out;

    int n = in_sizes[0] / DD;
    int e = in_sizes[1] / 2;
    const int* src = ei;
    const int* dst = ei + e;

    float* hbuf; cudaGetSymbolAddress((void**)&hbuf, g_h);
    float* buf;  cudaGetSymbolAddress((void**)&buf,  g_buf);

    // ---- CSR build ----
    int sblks = (n + SCAN_BLK - 1) / SCAN_BLK;
    k_zero<<<(n + 255) / 256, 256>>>(n);
    k_count_deg<<<(e + 255) / 256, 256>>>(dst, e);
    k_dinv<<<(n + 255) / 256, 256>>>(n);
    k_scan1<<<sblks, SCAN_BLK>>>(n);
    k_scan2<<<1, MAX_SBLKS>>>(sblks, n);
    k_scan3<<<sblks, SCAN_BLK>>>(n);
    k_fill<<<(e + 255) / 256, 256>>>(src, dst, e);

    int gemm_blocks = (n + 63) / 64;
    int pull_blocks = (n + 15) / 16;

    const float* cur_in = x;
    for (int l = 0; l < 4; l++) {
        float* layer_out = (l == 3) ? outp : buf;
        k_gemm<<<gemm_blocks, 256>>>(cur_in, W[l], hbuf, n, l > 0 ? 1 : 0);
        k_pull<<<pull_blocks, 256>>>(hbuf, B[l], layer_out, n, (l == 3) ? 1 : 0);
        cur_in = buf;
    }
}